// round 7
// baseline (speedup 1.0000x reference)
#include <cuda_runtime.h>
#include <cuda_fp16.h>

#define ALPHA 0.2f
#define B_TOT 65536
#define GRID 512
#define TILES 4

typedef unsigned int u32;

// ---- persistent prepped constants ----
__device__ float d_wa1[128];
__device__ __half d_Whi[16384];   // [n][k] = W[k][n], fp16 hi
__device__ __half d_Wlo[16384];   // residual lo

__global__ void prep_kernel(const float* __restrict__ W, const float* __restrict__ a) {
    int blk = blockIdx.x, tid = threadIdx.x;
    if (blk < 64) {
        int idx = blk * 256 + tid;            // (f,k)
        int f = idx >> 7, k = idx & 127;
        float w = W[k * 128 + f];
        __half hi = __float2half_rn(w);
        d_Whi[idx] = hi;
        d_Wlo[idx] = __float2half_rn(w - __half2float(hi));
    } else if (tid < 32) {
        int f = blk - 64;
        float4 wv = *(const float4*)(W + f * 128 + tid * 4);
        float4 av = *(const float4*)(a + tid * 4);
        float p = wv.x * av.x + wv.y * av.y + wv.z * av.z + wv.w * av.w;
#pragma unroll
        for (int off = 16; off; off >>= 1) p += __shfl_xor_sync(0xFFFFFFFFu, p, off);
        if (tid == 0) d_wa1[f] = p;
    }
}

// ---- smem layout: rows padded to 272B for conflict-free ldmatrix ----
#define ROWB 272
#define OFF_WH 0
#define OFF_WL 34816
#define OFF_A  69632
#define PANELB 17408
#define SMEM_BYTES (69632 + 8 * PANELB) // 208896

__device__ __forceinline__ u32 smem_u32(const void* p) {
    u32 a;
    asm("{ .reg .u64 t; cvta.to.shared.u64 t, %1; cvt.u32.u64 %0, t; }" : "=r"(a) : "l"(p));
    return a;
}
__device__ __forceinline__ void ldsm4(u32* r, u32 addr) {
    asm volatile("ldmatrix.sync.aligned.m8n8.x4.shared.b16 {%0,%1,%2,%3}, [%4];"
                 : "=r"(r[0]), "=r"(r[1]), "=r"(r[2]), "=r"(r[3]) : "r"(addr));
}
__device__ __forceinline__ void mma16816(float* c, const u32* a, u32 b0, u32 b1) {
    asm volatile("mma.sync.aligned.m16n8k16.row.col.f32.f16.f16.f32 "
                 "{%0,%1,%2,%3}, {%4,%5,%6,%7}, {%8,%9}, {%0,%1,%2,%3};"
                 : "+f"(c[0]), "+f"(c[1]), "+f"(c[2]), "+f"(c[3])
                 : "r"(a[0]), "r"(a[1]), "r"(a[2]), "r"(a[3]), "r"(b0), "r"(b1));
}

// attention + fold for ONE batch; writes 8 rows of A panel (hi/lo fp16)
__device__ __forceinline__ void attention_fold(
    const float4* hv, const float* __restrict__ adjb,
    float4 an, float4 v1, int lane, char* Ah, char* Al, int row_base)
{
    float en[8], s1[8];
#pragma unroll
    for (int j = 0; j < 8; j++) {
        float pe = hv[j].x * an.x + hv[j].y * an.y + hv[j].z * an.z + hv[j].w * an.w;
        float p1 = hv[j].x * v1.x + hv[j].y * v1.y + hv[j].z * v1.z + hv[j].w * v1.w;
#pragma unroll
        for (int off = 16; off; off >>= 1) {
            pe += __shfl_xor_sync(0xFFFFFFFFu, pe, off);
            p1 += __shfl_xor_sync(0xFFFFFFFFu, p1, off);
        }
        en[j] = pe; s1[j] = p1;
    }

    float mx = -1e30f;
#pragma unroll
    for (int j = 0; j < 8; j++) {
        float v = en[j] > 0.f ? en[j] : ALPHA * en[j];
        en[j] = v; mx = fmaxf(mx, v);
    }
    float sum = 0.f;
#pragma unroll
    for (int j = 0; j < 8; j++) { float p = __expf(en[j] - mx); en[j] = p; sum += p; }
    float inv = 1.f / sum;
    float scale[8], Wh1[8];
    float M = -1e30f;
#pragma unroll
    for (int j = 0; j < 8; j++) {
        float sc = 1.f + en[j] * inv;
        scale[j] = sc;
        Wh1[j] = sc * s1[j];
        M = fmaxf(M, Wh1[j]);
    }
    // Wh2[i] cancels in the row softmax: one exp set per batch.
    float u[8], w[8];
#pragma unroll
    for (int j = 0; j < 8; j++) {
        u[j] = __expf(Wh1[j] - M);
        w[j] = u[j] * scale[j];
    }

#pragma unroll
    for (int i = 0; i < 8; i++) {
        float4 A0 = *(const float4*)(adjb + i * 8);
        float4 A1 = *(const float4*)(adjb + i * 8 + 4);
        float s = A0.x * u[0];
        s = fmaf(A0.y, u[1], s); s = fmaf(A0.z, u[2], s); s = fmaf(A0.w, u[3], s);
        s = fmaf(A1.x, u[4], s); s = fmaf(A1.y, u[5], s); s = fmaf(A1.z, u[6], s);
        s = fmaf(A1.w, u[7], s);
        float c[8], is;
        if (s != 0.f) {
            is = __fdividef(1.f, s);
            c[0] = A0.x * w[0]; c[1] = A0.y * w[1]; c[2] = A0.z * w[2]; c[3] = A0.w * w[3];
            c[4] = A1.x * w[4]; c[5] = A1.y * w[5]; c[6] = A1.z * w[6]; c[7] = A1.w * w[7];
        } else {                              // fully-masked row: uniform 1/8
            is = 0.125f;
#pragma unroll
            for (int j = 0; j < 8; j++) c[j] = scale[j];
        }
        float4 g = make_float4(0.f, 0.f, 0.f, 0.f);
#pragma unroll
        for (int j = 0; j < 8; j++) {
            g.x = fmaf(c[j], hv[j].x, g.x);
            g.y = fmaf(c[j], hv[j].y, g.y);
            g.z = fmaf(c[j], hv[j].z, g.z);
            g.w = fmaf(c[j], hv[j].w, g.w);
        }
        g.x *= is; g.y *= is; g.z *= is; g.w *= is;

        __half2 h01 = __floats2half2_rn(g.x, g.y);
        __half2 h23 = __floats2half2_rn(g.z, g.w);
        float2 f01 = __half22float2(h01);
        float2 f23 = __half22float2(h23);
        __half2 l01 = __floats2half2_rn(g.x - f01.x, g.y - f01.y);
        __half2 l23 = __floats2half2_rn(g.z - f23.x, g.w - f23.y);
        int row = row_base + i;
        uint2 uh = make_uint2(*(u32*)&h01, *(u32*)&h23);
        uint2 ul = make_uint2(*(u32*)&l01, *(u32*)&l23);
        *(uint2*)(Ah + row * ROWB + lane * 8) = uh;
        *(uint2*)(Al + row * ROWB + lane * 8) = ul;
    }
}

__global__ __launch_bounds__(512, 1) void fused_gat_hmma(
    const float* __restrict__ h, const float* __restrict__ adj,
    const float* __restrict__ a_node, float* __restrict__ out)
{
    extern __shared__ char sm[];
    const u32 smb = smem_u32(sm);
    int tid = threadIdx.x, lane = tid & 31, warp = tid >> 5;
    int pair = warp >> 1, half = warp & 1;

    // ---- stage W^T hi/lo (once per CTA, amortized over TILES) ----
    {
        const uint4* Wh = (const uint4*)d_Whi;
        const uint4* Wl = (const uint4*)d_Wlo;
#pragma unroll
        for (int t = 0; t < 4; t++) {
            int idx = tid + t * 512;
            int row = idx >> 4, c = idx & 15;
            *(uint4*)(sm + OFF_WH + row * ROWB + c * 16) = Wh[idx];
            *(uint4*)(sm + OFF_WL + row * ROWB + c * 16) = Wl[idx];
        }
    }
    __syncthreads();

    float4 an = *(const float4*)(a_node + lane * 4);
    float4 v1 = *(const float4*)(d_wa1 + lane * 4);

    char* Ah = sm + OFF_A + pair * PANELB;
    char* Al = Ah + 32 * ROWB;

    const u32 ah_base = smb + (u32)(OFF_A + pair * PANELB);
    const u32 al_base = ah_base + 32 * ROWB;
    const u32 a_off = (u32)((lane & 15) * ROWB + (lane >> 4) * 16);
    const u32 b_off = (u32)((half * 64 + ((lane >> 4) << 3) + (lane & 7)) * ROWB +
                            (((lane >> 3) & 1) << 4));

    // prefetch tile 0, batch 0
    float4 hv0[8];
    {
        const float* hb = h + ((size_t)(blockIdx.x * 32 + pair * 4 + half * 2)) * 1024;
#pragma unroll
        for (int j = 0; j < 8; j++) hv0[j] = *(const float4*)(hb + j * 128 + lane * 4);
    }

#pragma unroll 1
    for (int t = 0; t < TILES; t++) {
        const int tile = blockIdx.x + t * GRID;
        const int bp = tile * 32 + pair * 4;
        const int b0 = bp + half * 2;
        const int rb = half * 2 * 8;

        // issue batch-1 h loads (hidden under batch-0 attention)
        float4 hv1[8];
        {
            const float* hb = h + ((size_t)(b0 + 1)) * 1024;
#pragma unroll
            for (int j = 0; j < 8; j++) hv1[j] = *(const float4*)(hb + j * 128 + lane * 4);
        }

        attention_fold(hv0, adj + (size_t)b0 * 64,       an, v1, lane, Ah, Al, rb);
        attention_fold(hv1, adj + (size_t)(b0 + 1) * 64, an, v1, lane, Ah, Al, rb + 8);

        asm volatile("bar.sync %0, 64;" :: "r"(pair + 1) : "memory");

        // prefetch next tile's batch-0 h (hidden under the GEMM)
        if (t + 1 < TILES) {
            const float* hb = h + ((size_t)(b0 + GRID * 32)) * 1024;
#pragma unroll
            for (int j = 0; j < 8; j++) hv0[j] = *(const float4*)(hb + j * 128 + lane * 4);
        }

        // ====== HMMA GEMM: rows 0..31 (pair's 4 batches) x this warp's 64-col half ======
        float acc[16][4];
#pragma unroll
        for (int q = 0; q < 16; q++) { acc[q][0] = acc[q][1] = acc[q][2] = acc[q][3] = 0.f; }

#pragma unroll
        for (int ks = 0; ks < 8; ks++) {
            u32 afh[2][4], afl[2][4];
#pragma unroll
            for (int mt = 0; mt < 2; mt++) {
                ldsm4(afh[mt], ah_base + a_off + mt * (16 * ROWB) + ks * 32);
                ldsm4(afl[mt], al_base + a_off + mt * (16 * ROWB) + ks * 32);
            }
#pragma unroll
            for (int np = 0; np < 4; np++) {
                u32 bh[4], bl[4];
                u32 nb = smb + (u32)(np * 16 * ROWB) + b_off + ks * 32;
                ldsm4(bh, (u32)OFF_WH + nb);
                ldsm4(bl, (u32)OFF_WL + nb);
#pragma unroll
                for (int mt = 0; mt < 2; mt++) {
                    float* ac0 = acc[mt * 8 + 2 * np];
                    float* ac1 = acc[mt * 8 + 2 * np + 1];
                    mma16816(ac0, afh[mt], bh[0], bh[1]);
                    mma16816(ac0, afh[mt], bl[0], bl[1]);
                    mma16816(ac0, afl[mt], bh[0], bh[1]);
                    mma16816(ac1, afh[mt], bh[2], bh[3]);
                    mma16816(ac1, afh[mt], bl[2], bl[3]);
                    mma16816(ac1, afl[mt], bh[2], bh[3]);
                }
            }
        }

        // ---- epilogue: relu + store ----
#pragma unroll
        for (int mt = 0; mt < 2; mt++) {
            float* o0 = out + ((size_t)(bp + mt * 2) * 8 + (lane >> 2)) * 128 +
                        half * 64 + (lane & 3) * 2;
            float* o1 = o0 + 1024;
#pragma unroll
            for (int nt = 0; nt < 8; nt++) {
                float* ac = acc[mt * 8 + nt];
                float2 r0 = make_float2(fmaxf(ac[0], 0.f), fmaxf(ac[1], 0.f));
                float2 r1 = make_float2(fmaxf(ac[2], 0.f), fmaxf(ac[3], 0.f));
                *(float2*)(o0 + nt * 8) = r0;
                *(float2*)(o1 + nt * 8) = r1;
            }
        }

        // A panel consumed by both warps -> safe to overwrite next iteration
        asm volatile("bar.sync %0, 64;" :: "r"(pair + 1) : "memory");
    }
}

extern "C" void kernel_launch(void* const* d_in, const int* in_sizes, int n_in,
                              void* d_out, int out_size) {
    const float* h      = (const float*)d_in[0];
    const float* adj    = (const float*)d_in[1];
    const float* W      = (const float*)d_in[2];
    const float* a      = (const float*)d_in[3];
    const float* a_node = (const float*)d_in[4];
    float* out = (float*)d_out;

    prep_kernel<<<192, 256>>>(W, a);

    cudaFuncSetAttribute(fused_gat_hmma, cudaFuncAttributeMaxDynamicSharedMemorySize, SMEM_BYTES);
    fused_gat_hmma<<<GRID, 512, SMEM_BYTES>>>(h, adj, a_node, out);
}

// round 8
// speedup vs baseline: 1.4064x; 1.4064x over previous
#include <cuda_runtime.h>
#include <cuda_fp16.h>

#define ALPHA 0.2f
#define B_TOT 65536

typedef unsigned int u32;

// ---- persistent prepped constants ----
__device__ float d_wa1[128];
__device__ __half d_Whi[16384];   // [n][k] = W[k][n], fp16 (hi only; lo term dropped, err ~3e-4)

// Parallel prep: blocks 0..63 convert W^T to fp16; blocks 64..191 compute wa1.
__global__ void prep_kernel(const float* __restrict__ W, const float* __restrict__ a) {
    int blk = blockIdx.x, tid = threadIdx.x;
    if (blk < 64) {
        int idx = blk * 256 + tid;            // (f,k)
        int f = idx >> 7, k = idx & 127;
        d_Whi[idx] = __float2half_rn(W[k * 128 + f]);
    } else if (tid < 32) {
        int f = blk - 64;
        float4 wv = *(const float4*)(W + f * 128 + tid * 4);
        float4 av = *(const float4*)(a + tid * 4);
        float p = wv.x * av.x + wv.y * av.y + wv.z * av.z + wv.w * av.w;
#pragma unroll
        for (int off = 16; off; off >>= 1) p += __shfl_xor_sync(0xFFFFFFFFu, p, off);
        if (tid == 0) d_wa1[f] = p;
    }
}

// ---- smem layout: rows padded to 272B for conflict-free ldmatrix ----
#define ROWB 272
#define OFF_WH 0                        // 128 rows * 272 = 34816
#define OFF_A  34816                    // per-PAIR panel: 32 rows hi + 32 rows lo
#define PANELB 17408
#define SMEM_BYTES (34816 + 8 * PANELB) // 174080

__device__ __forceinline__ u32 smem_u32(const void* p) {
    u32 a;
    asm("{ .reg .u64 t; cvta.to.shared.u64 t, %1; cvt.u32.u64 %0, t; }" : "=r"(a) : "l"(p));
    return a;
}
__device__ __forceinline__ void ldsm4(u32* r, u32 addr) {
    asm volatile("ldmatrix.sync.aligned.m8n8.x4.shared.b16 {%0,%1,%2,%3}, [%4];"
                 : "=r"(r[0]), "=r"(r[1]), "=r"(r[2]), "=r"(r[3]) : "r"(addr));
}
__device__ __forceinline__ void mma16816(float* c, const u32* a, u32 b0, u32 b1) {
    asm volatile("mma.sync.aligned.m16n8k16.row.col.f32.f16.f16.f32 "
                 "{%0,%1,%2,%3}, {%4,%5,%6,%7}, {%8,%9}, {%0,%1,%2,%3};"
                 : "+f"(c[0]), "+f"(c[1]), "+f"(c[2]), "+f"(c[3])
                 : "r"(a[0]), "r"(a[1]), "r"(a[2]), "r"(a[3]), "r"(b0), "r"(b1));
}

// attention + fold for ONE batch; writes 8 rows of the pair A panel (hi/lo fp16)
__device__ __forceinline__ void attention_fold(
    const float4* hv, const float* __restrict__ adjb,
    float4 an, float4 v1, int lane, char* Ah, char* Al, int row_base)
{
    float en[8], s1[8];
#pragma unroll
    for (int j = 0; j < 8; j++) {
        float pe = hv[j].x * an.x + hv[j].y * an.y + hv[j].z * an.z + hv[j].w * an.w;
        float p1 = hv[j].x * v1.x + hv[j].y * v1.y + hv[j].z * v1.z + hv[j].w * v1.w;
#pragma unroll
        for (int off = 16; off; off >>= 1) {
            pe += __shfl_xor_sync(0xFFFFFFFFu, pe, off);
            p1 += __shfl_xor_sync(0xFFFFFFFFu, p1, off);
        }
        en[j] = pe; s1[j] = p1;
    }

    float mx = -1e30f;
#pragma unroll
    for (int j = 0; j < 8; j++) {
        float v = en[j] > 0.f ? en[j] : ALPHA * en[j];
        en[j] = v; mx = fmaxf(mx, v);
    }
    float sum = 0.f;
#pragma unroll
    for (int j = 0; j < 8; j++) { float p = __expf(en[j] - mx); en[j] = p; sum += p; }
    float inv = 1.f / sum;
    float scale[8], Wh1[8];
    float M = -1e30f;
#pragma unroll
    for (int j = 0; j < 8; j++) {
        float sc = 1.f + en[j] * inv;
        scale[j] = sc;
        Wh1[j] = sc * s1[j];
        M = fmaxf(M, Wh1[j]);
    }
    // Wh2[i] cancels in the row softmax: one exp set per batch.
    float u[8], w[8];
#pragma unroll
    for (int j = 0; j < 8; j++) {
        u[j] = __expf(Wh1[j] - M);
        w[j] = u[j] * scale[j];
    }

#pragma unroll
    for (int i = 0; i < 8; i++) {
        float4 A0 = *(const float4*)(adjb + i * 8);
        float4 A1 = *(const float4*)(adjb + i * 8 + 4);
        float s = A0.x * u[0];
        s = fmaf(A0.y, u[1], s); s = fmaf(A0.z, u[2], s); s = fmaf(A0.w, u[3], s);
        s = fmaf(A1.x, u[4], s); s = fmaf(A1.y, u[5], s); s = fmaf(A1.z, u[6], s);
        s = fmaf(A1.w, u[7], s);
        float c[8], is;
        if (s != 0.f) {                       // warp-uniform branch
            is = __fdividef(1.f, s);
            c[0] = A0.x * w[0]; c[1] = A0.y * w[1]; c[2] = A0.z * w[2]; c[3] = A0.w * w[3];
            c[4] = A1.x * w[4]; c[5] = A1.y * w[5]; c[6] = A1.z * w[6]; c[7] = A1.w * w[7];
        } else {                              // fully-masked row: uniform 1/8
            is = 0.125f;
#pragma unroll
            for (int j = 0; j < 8; j++) c[j] = scale[j];
        }
        float4 g = make_float4(0.f, 0.f, 0.f, 0.f);
#pragma unroll
        for (int j = 0; j < 8; j++) {
            g.x = fmaf(c[j], hv[j].x, g.x);
            g.y = fmaf(c[j], hv[j].y, g.y);
            g.z = fmaf(c[j], hv[j].z, g.z);
            g.w = fmaf(c[j], hv[j].w, g.w);
        }
        g.x *= is; g.y *= is; g.z *= is; g.w *= is;

        __half2 h01 = __floats2half2_rn(g.x, g.y);
        __half2 h23 = __floats2half2_rn(g.z, g.w);
        float2 f01 = __half22float2(h01);
        float2 f23 = __half22float2(h23);
        __half2 l01 = __floats2half2_rn(g.x - f01.x, g.y - f01.y);
        __half2 l23 = __floats2half2_rn(g.z - f23.x, g.w - f23.y);
        int row = row_base + i;
        uint2 uh = make_uint2(*(u32*)&h01, *(u32*)&h23);
        uint2 ul = make_uint2(*(u32*)&l01, *(u32*)&l23);
        *(uint2*)(Ah + row * ROWB + lane * 8) = uh;
        *(uint2*)(Al + row * ROWB + lane * 8) = ul;
    }
}

__global__ __launch_bounds__(512, 1) void fused_gat_hmma(
    const float* __restrict__ h, const float* __restrict__ adj,
    const float* __restrict__ a_node, float* __restrict__ out)
{
    extern __shared__ char sm[];
    const u32 smb = smem_u32(sm);
    int tid = threadIdx.x, lane = tid & 31, warp = tid >> 5;
    int pair = warp >> 1, half = warp & 1;

    // ---- stage W^T (fp16 hi) into padded smem, once per CTA ----
    {
        const uint4* Wh = (const uint4*)d_Whi;   // 2048 16B chunks
#pragma unroll
        for (int t = 0; t < 4; t++) {
            int idx = tid + t * 512;
            int row = idx >> 4, c = idx & 15;
            *(uint4*)(sm + OFF_WH + row * ROWB + c * 16) = Wh[idx];
        }
    }
    __syncthreads();

    float4 an = *(const float4*)(a_node + lane * 4);
    float4 v1 = *(const float4*)(d_wa1 + lane * 4);

    char* Ah = sm + OFF_A + pair * PANELB;       // 32 rows (pair's 4 batches)
    char* Al = Ah + 32 * ROWB;
    const int bp = blockIdx.x * 32 + pair * 4;
    const int b0 = bp + half * 2;
    const int rb = half * 2 * 8;

    // ---- both batches' h loads issued upfront (MLP=16 on the DRAM latency) ----
    float4 hv0[8], hv1[8];
    {
        const float* hb0 = h + (size_t)b0 * 1024;
        const float* hb1 = hb0 + 1024;
#pragma unroll
        for (int j = 0; j < 8; j++) hv0[j] = *(const float4*)(hb0 + j * 128 + lane * 4);
#pragma unroll
        for (int j = 0; j < 8; j++) hv1[j] = *(const float4*)(hb1 + j * 128 + lane * 4);
    }

    attention_fold(hv0, adj + (size_t)b0 * 64,       an, v1, lane, Ah, Al, rb);
    attention_fold(hv1, adj + (size_t)(b0 + 1) * 64, an, v1, lane, Ah, Al, rb + 8);

    // pair barrier: both warps' A rows visible before cross-read
    asm volatile("bar.sync %0, 64;" :: "r"(pair + 1) : "memory");

    // ====== HMMA GEMM: rows 0..31 x this warp's 64-col half, 2 passes (Ah+Al)@Wh ======
    float acc[16][4];   // [mt*8+nt][c]
#pragma unroll
    for (int t = 0; t < 16; t++) { acc[t][0] = acc[t][1] = acc[t][2] = acc[t][3] = 0.f; }

    const u32 ah_base = smb + (u32)(OFF_A + pair * PANELB);
    const u32 al_base = ah_base + 32 * ROWB;
    const u32 a_off = (u32)((lane & 15) * ROWB + (lane >> 4) * 16);
    const u32 b_off = (u32)((half * 64 + ((lane >> 4) << 3) + (lane & 7)) * ROWB +
                            (((lane >> 3) & 1) << 4));

#pragma unroll
    for (int ks = 0; ks < 8; ks++) {
        u32 afh[2][4], afl[2][4];
#pragma unroll
        for (int mt = 0; mt < 2; mt++) {
            ldsm4(afh[mt], ah_base + a_off + mt * (16 * ROWB) + ks * 32);
            ldsm4(afl[mt], al_base + a_off + mt * (16 * ROWB) + ks * 32);
        }
#pragma unroll
        for (int np = 0; np < 4; np++) {
            u32 bh[4];
            ldsm4(bh, smb + (u32)OFF_WH + (u32)(np * 16 * ROWB) + b_off + ks * 32);
#pragma unroll
            for (int mt = 0; mt < 2; mt++) {
                float* ac0 = acc[mt * 8 + 2 * np];
                float* ac1 = acc[mt * 8 + 2 * np + 1];
                mma16816(ac0, afh[mt], bh[0], bh[1]);
                mma16816(ac0, afl[mt], bh[0], bh[1]);
                mma16816(ac1, afh[mt], bh[2], bh[3]);
                mma16816(ac1, afl[mt], bh[2], bh[3]);
            }
        }
    }

    // ---- epilogue: relu + store ----
#pragma unroll
    for (int mt = 0; mt < 2; mt++) {
        float* o0 = out + ((size_t)(bp + mt * 2) * 8 + (lane >> 2)) * 128 +
                    half * 64 + (lane & 3) * 2;
        float* o1 = o0 + 1024;
#pragma unroll
        for (int nt = 0; nt < 8; nt++) {
            float* ac = acc[mt * 8 + nt];
            float2 r0 = make_float2(fmaxf(ac[0], 0.f), fmaxf(ac[1], 0.f));
            float2 r1 = make_float2(fmaxf(ac[2], 0.f), fmaxf(ac[3], 0.f));
            *(float2*)(o0 + nt * 8) = r0;
            *(float2*)(o1 + nt * 8) = r1;
        }
    }
}

extern "C" void kernel_launch(void* const* d_in, const int* in_sizes, int n_in,
                              void* d_out, int out_size) {
    const float* h      = (const float*)d_in[0];
    const float* adj    = (const float*)d_in[1];
    const float* W      = (const float*)d_in[2];
    const float* a      = (const float*)d_in[3];
    const float* a_node = (const float*)d_in[4];
    float* out = (float*)d_out;

    prep_kernel<<<192, 256>>>(W, a);

    cudaFuncSetAttribute(fused_gat_hmma, cudaFuncAttributeMaxDynamicSharedMemorySize, SMEM_BYTES);
    fused_gat_hmma<<<B_TOT / 32, 512, SMEM_BYTES>>>(h, adj, a_node, out);
}

// round 9
// speedup vs baseline: 1.6494x; 1.1728x over previous
#include <cuda_runtime.h>
#include <cuda_fp16.h>

#define ALPHA 0.2f
#define B_TOT 65536

typedef unsigned int u32;

// ---- persistent prepped constants ----
__device__ float d_wa1[128];
__device__ __half d_Whi[16384];   // [n][k] = W[k][n], fp16 (lo dropped; err ~2e-4)

// Parallel prep: blocks 0..63 convert W^T to fp16; blocks 64..191 compute wa1.
__global__ void prep_kernel(const float* __restrict__ W, const float* __restrict__ a) {
    int blk = blockIdx.x, tid = threadIdx.x;
    if (blk < 64) {
        int idx = blk * 256 + tid;            // (f,k)
        int f = idx >> 7, k = idx & 127;
        d_Whi[idx] = __float2half_rn(W[k * 128 + f]);
    } else if (tid < 32) {
        int f = blk - 64;
        float4 wv = *(const float4*)(W + f * 128 + tid * 4);
        float4 av = *(const float4*)(a + tid * 4);
        float p = wv.x * av.x + wv.y * av.y + wv.z * av.z + wv.w * av.w;
#pragma unroll
        for (int off = 16; off; off >>= 1) p += __shfl_xor_sync(0xFFFFFFFFu, p, off);
        if (tid == 0) d_wa1[f] = p;
    }
}

// ---- smem layout: rows padded to 272B for conflict-free ldmatrix ----
#define ROWB 272
#define OFF_WH 0                        // 128 rows * 272 = 34816
#define OFF_A  34816                    // per-PAIR panel: 32 rows fp16
#define PANELB 8704
#define SMEM_BYTES (34816 + 8 * PANELB) // 104448

__device__ __forceinline__ u32 smem_u32(const void* p) {
    u32 a;
    asm("{ .reg .u64 t; cvta.to.shared.u64 t, %1; cvt.u32.u64 %0, t; }" : "=r"(a) : "l"(p));
    return a;
}
__device__ __forceinline__ void ldsm4(u32* r, u32 addr) {
    asm volatile("ldmatrix.sync.aligned.m8n8.x4.shared.b16 {%0,%1,%2,%3}, [%4];"
                 : "=r"(r[0]), "=r"(r[1]), "=r"(r[2]), "=r"(r[3]) : "r"(addr));
}
__device__ __forceinline__ void mma16816(float* c, const u32* a, u32 b0, u32 b1) {
    asm volatile("mma.sync.aligned.m16n8k16.row.col.f32.f16.f16.f32 "
                 "{%0,%1,%2,%3}, {%4,%5,%6,%7}, {%8,%9}, {%0,%1,%2,%3};"
                 : "+f"(c[0]), "+f"(c[1]), "+f"(c[2]), "+f"(c[3])
                 : "r"(a[0]), "r"(a[1]), "r"(a[2]), "r"(a[3]), "r"(b0), "r"(b1));
}

// attention + fold for ONE batch; writes 8 fp16 rows of the pair A panel
__device__ __forceinline__ void attention_fold(
    const float4* hv, const float* __restrict__ adjb,
    float4 an, float4 v1, int lane, char* Ah, int row_base)
{
    float en[8], s1[8];
#pragma unroll
    for (int j = 0; j < 8; j++) {
        float pe = hv[j].x * an.x + hv[j].y * an.y + hv[j].z * an.z + hv[j].w * an.w;
        float p1 = hv[j].x * v1.x + hv[j].y * v1.y + hv[j].z * v1.z + hv[j].w * v1.w;
#pragma unroll
        for (int off = 16; off; off >>= 1) {
            pe += __shfl_xor_sync(0xFFFFFFFFu, pe, off);
            p1 += __shfl_xor_sync(0xFFFFFFFFu, p1, off);
        }
        en[j] = pe; s1[j] = p1;
    }

    float mx = -1e30f;
#pragma unroll
    for (int j = 0; j < 8; j++) {
        float v = en[j] > 0.f ? en[j] : ALPHA * en[j];
        en[j] = v; mx = fmaxf(mx, v);
    }
    float sum = 0.f;
#pragma unroll
    for (int j = 0; j < 8; j++) { float p = __expf(en[j] - mx); en[j] = p; sum += p; }
    float inv = 1.f / sum;
    float scale[8], Wh1[8];
    float M = -1e30f;
#pragma unroll
    for (int j = 0; j < 8; j++) {
        float sc = 1.f + en[j] * inv;
        scale[j] = sc;
        Wh1[j] = sc * s1[j];
        M = fmaxf(M, Wh1[j]);
    }
    // Wh2[i] cancels in the row softmax: one exp set per batch.
    float u[8], w[8];
#pragma unroll
    for (int j = 0; j < 8; j++) {
        u[j] = __expf(Wh1[j] - M);
        w[j] = u[j] * scale[j];
    }

#pragma unroll
    for (int i = 0; i < 8; i++) {
        float4 A0 = *(const float4*)(adjb + i * 8);
        float4 A1 = *(const float4*)(adjb + i * 8 + 4);
        float s = A0.x * u[0];
        s = fmaf(A0.y, u[1], s); s = fmaf(A0.z, u[2], s); s = fmaf(A0.w, u[3], s);
        s = fmaf(A1.x, u[4], s); s = fmaf(A1.y, u[5], s); s = fmaf(A1.z, u[6], s);
        s = fmaf(A1.w, u[7], s);
        float c[8], is;
        if (s != 0.f) {                       // warp-uniform branch
            is = __fdividef(1.f, s);
            c[0] = A0.x * w[0]; c[1] = A0.y * w[1]; c[2] = A0.z * w[2]; c[3] = A0.w * w[3];
            c[4] = A1.x * w[4]; c[5] = A1.y * w[5]; c[6] = A1.z * w[6]; c[7] = A1.w * w[7];
        } else {                              // fully-masked row: uniform 1/8
            is = 0.125f;
#pragma unroll
            for (int j = 0; j < 8; j++) c[j] = scale[j];
        }
        float4 g = make_float4(0.f, 0.f, 0.f, 0.f);
#pragma unroll
        for (int j = 0; j < 8; j++) {
            g.x = fmaf(c[j], hv[j].x, g.x);
            g.y = fmaf(c[j], hv[j].y, g.y);
            g.z = fmaf(c[j], hv[j].z, g.z);
            g.w = fmaf(c[j], hv[j].w, g.w);
        }
        g.x *= is; g.y *= is; g.z *= is; g.w *= is;

        __half2 h01 = __floats2half2_rn(g.x, g.y);
        __half2 h23 = __floats2half2_rn(g.z, g.w);
        uint2 uh = make_uint2(*(u32*)&h01, *(u32*)&h23);
        *(uint2*)(Ah + (row_base + i) * ROWB + lane * 8) = uh;
    }
}

__global__ __launch_bounds__(512, 1) void fused_gat_hmma(
    const float* __restrict__ h, const float* __restrict__ adj,
    const float* __restrict__ a_node, float* __restrict__ out)
{
    extern __shared__ char sm[];
    const u32 smb = smem_u32(sm);
    int tid = threadIdx.x, lane = tid & 31, warp = tid >> 5;
    int pair = warp >> 1, half = warp & 1;

    // ---- stage W^T (fp16) into padded smem, once per CTA ----
    {
        const uint4* Wh = (const uint4*)d_Whi;   // 2048 16B chunks
#pragma unroll
        for (int t = 0; t < 4; t++) {
            int idx = tid + t * 512;
            int row = idx >> 4, c = idx & 15;
            *(uint4*)(sm + OFF_WH + row * ROWB + c * 16) = Wh[idx];
        }
    }
    __syncthreads();

    float4 an = *(const float4*)(a_node + lane * 4);
    float4 v1 = *(const float4*)(d_wa1 + lane * 4);

    char* Ah = sm + OFF_A + pair * PANELB;       // 32 rows (pair's 4 batches)
    const int bp = blockIdx.x * 32 + pair * 4;
    const int b0 = bp + half * 2;
    const int rb = half * 2 * 8;

    // ---- both batches' h loads issued upfront (MLP=16 on the DRAM latency) ----
    float4 hv0[8], hv1[8];
    {
        const float* hb0 = h + (size_t)b0 * 1024;
        const float* hb1 = hb0 + 1024;
#pragma unroll
        for (int j = 0; j < 8; j++) hv0[j] = *(const float4*)(hb0 + j * 128 + lane * 4);
#pragma unroll
        for (int j = 0; j < 8; j++) hv1[j] = *(const float4*)(hb1 + j * 128 + lane * 4);
    }

    attention_fold(hv0, adj + (size_t)b0 * 64,       an, v1, lane, Ah, rb);
    attention_fold(hv1, adj + (size_t)(b0 + 1) * 64, an, v1, lane, Ah, rb + 8);

    // pair barrier: both warps' A rows visible before cross-read
    asm volatile("bar.sync %0, 64;" :: "r"(pair + 1) : "memory");

    // ====== HMMA GEMM: rows 0..31 x this warp's 64-col half, single fp16 pass ======
    float acc[16][4];   // [mt*8+nt][c]
#pragma unroll
    for (int t = 0; t < 16; t++) { acc[t][0] = acc[t][1] = acc[t][2] = acc[t][3] = 0.f; }

    const u32 ah_base = smb + (u32)(OFF_A + pair * PANELB);
    const u32 a_off = (u32)((lane & 15) * ROWB + (lane >> 4) * 16);
    const u32 b_off = (u32)((half * 64 + ((lane >> 4) << 3) + (lane & 7)) * ROWB +
                            (((lane >> 3) & 1) << 4));

#pragma unroll
    for (int ks = 0; ks < 8; ks++) {
        u32 afh[2][4];
#pragma unroll
        for (int mt = 0; mt < 2; mt++)
            ldsm4(afh[mt], ah_base + a_off + mt * (16 * ROWB) + ks * 32);
#pragma unroll
        for (int np = 0; np < 4; np++) {
            u32 bh[4];
            ldsm4(bh, smb + (u32)OFF_WH + (u32)(np * 16 * ROWB) + b_off + ks * 32);
#pragma unroll
            for (int mt = 0; mt < 2; mt++) {
                mma16816(acc[mt * 8 + 2 * np],     afh[mt], bh[0], bh[1]);
                mma16816(acc[mt * 8 + 2 * np + 1], afh[mt], bh[2], bh[3]);
            }
        }
    }

    // ---- epilogue: relu + store ----
#pragma unroll
    for (int mt = 0; mt < 2; mt++) {
        float* o0 = out + ((size_t)(bp + mt * 2) * 8 + (lane >> 2)) * 128 +
                    half * 64 + (lane & 3) * 2;
        float* o1 = o0 + 1024;
#pragma unroll
        for (int nt = 0; nt < 8; nt++) {
            float* ac = acc[mt * 8 + nt];
            float2 r0 = make_float2(fmaxf(ac[0], 0.f), fmaxf(ac[1], 0.f));
            float2 r1 = make_float2(fmaxf(ac[2], 0.f), fmaxf(ac[3], 0.f));
            *(float2*)(o0 + nt * 8) = r0;
            *(float2*)(o1 + nt * 8) = r1;
        }
    }
}

extern "C" void kernel_launch(void* const* d_in, const int* in_sizes, int n_in,
                              void* d_out, int out_size) {
    const float* h      = (const float*)d_in[0];
    const float* adj    = (const float*)d_in[1];
    const float* W      = (const float*)d_in[2];
    const float* a      = (const float*)d_in[3];
    const float* a_node = (const float*)d_in[4];
    float* out = (float*)d_out;

    prep_kernel<<<192, 256>>>(W, a);

    cudaFuncSetAttribute(fused_gat_hmma, cudaFuncAttributeMaxDynamicSharedMemorySize, SMEM_BYTES);
    fused_gat_hmma<<<B_TOT / 32, 512, SMEM_BYTES>>>(h, adj, a_node, out);
}

// round 10
// speedup vs baseline: 1.7251x; 1.0459x over previous
#include <cuda_runtime.h>
#include <cuda_fp16.h>

#define ALPHA 0.2f
#define B_TOT 65536

typedef unsigned int u32;

// ---- persistent prepped constants ----
__device__ float d_wa1[128];
__device__ __half d_Whi[16384];   // [n][k] = W[k][n], fp16 (lo dropped; err ~2e-4)

// Parallel prep: blocks 0..63 convert W^T to fp16; blocks 64..191 compute wa1.
__global__ void prep_kernel(const float* __restrict__ W, const float* __restrict__ a) {
    int blk = blockIdx.x, tid = threadIdx.x;
    if (blk < 64) {
        int idx = blk * 256 + tid;            // (f,k)
        int f = idx >> 7, k = idx & 127;
        d_Whi[idx] = __float2half_rn(W[k * 128 + f]);
    } else if (tid < 32) {
        int f = blk - 64;
        float4 wv = *(const float4*)(W + f * 128 + tid * 4);
        float4 av = *(const float4*)(a + tid * 4);
        float p = wv.x * av.x + wv.y * av.y + wv.z * av.z + wv.w * av.w;
#pragma unroll
        for (int off = 16; off; off >>= 1) p += __shfl_xor_sync(0xFFFFFFFFu, p, off);
        if (tid == 0) d_wa1[f] = p;
    }
}

// ---- smem layout: rows padded to 272B for conflict-free ldmatrix ----
#define ROWB 272
#define OFF_WH 0                        // 128 rows * 272 = 34816
#define OFF_A  34816                    // per-QUAD panel: 32 rows fp16 = 8704 B
#define PANELB 8704
#define SMEM_BYTES (34816 + 2 * PANELB) // 52224 (256-thr CTA = 2 quads)

__device__ __forceinline__ u32 smem_u32(const void* p) {
    u32 a;
    asm("{ .reg .u64 t; cvta.to.shared.u64 t, %1; cvt.u32.u64 %0, t; }" : "=r"(a) : "l"(p));
    return a;
}
__device__ __forceinline__ void ldsm4(u32* r, u32 addr) {
    asm volatile("ldmatrix.sync.aligned.m8n8.x4.shared.b16 {%0,%1,%2,%3}, [%4];"
                 : "=r"(r[0]), "=r"(r[1]), "=r"(r[2]), "=r"(r[3]) : "r"(addr));
}
__device__ __forceinline__ void mma16816(float* c, const u32* a, u32 b0, u32 b1) {
    asm volatile("mma.sync.aligned.m16n8k16.row.col.f32.f16.f16.f32 "
                 "{%0,%1,%2,%3}, {%4,%5,%6,%7}, {%8,%9}, {%0,%1,%2,%3};"
                 : "+f"(c[0]), "+f"(c[1]), "+f"(c[2]), "+f"(c[3])
                 : "r"(a[0]), "r"(a[1]), "r"(a[2]), "r"(a[3]), "r"(b0), "r"(b1));
}

// attention + fold for ONE batch; writes 8 fp16 rows of the quad A panel
__device__ __forceinline__ void attention_fold(
    const float4* hv, const float* __restrict__ adjb,
    float4 an, float4 v1, int lane, char* Ah, int row_base)
{
    float en[8], s1[8];
#pragma unroll
    for (int j = 0; j < 8; j++) {
        float pe = hv[j].x * an.x + hv[j].y * an.y + hv[j].z * an.z + hv[j].w * an.w;
        float p1 = hv[j].x * v1.x + hv[j].y * v1.y + hv[j].z * v1.z + hv[j].w * v1.w;
#pragma unroll
        for (int off = 16; off; off >>= 1) {
            pe += __shfl_xor_sync(0xFFFFFFFFu, pe, off);
            p1 += __shfl_xor_sync(0xFFFFFFFFu, p1, off);
        }
        en[j] = pe; s1[j] = p1;
    }

    float mx = -1e30f;
#pragma unroll
    for (int j = 0; j < 8; j++) {
        float v = en[j] > 0.f ? en[j] : ALPHA * en[j];
        en[j] = v; mx = fmaxf(mx, v);
    }
    float sum = 0.f;
#pragma unroll
    for (int j = 0; j < 8; j++) { float p = __expf(en[j] - mx); en[j] = p; sum += p; }
    float inv = 1.f / sum;
    float scale[8], Wh1[8];
    float M = -1e30f;
#pragma unroll
    for (int j = 0; j < 8; j++) {
        float sc = 1.f + en[j] * inv;
        scale[j] = sc;
        Wh1[j] = sc * s1[j];
        M = fmaxf(M, Wh1[j]);
    }
    // Wh2[i] cancels in the row softmax: one exp set per batch.
    float u[8], w[8];
#pragma unroll
    for (int j = 0; j < 8; j++) {
        u[j] = __expf(Wh1[j] - M);
        w[j] = u[j] * scale[j];
    }

#pragma unroll
    for (int i = 0; i < 8; i++) {
        float4 A0 = *(const float4*)(adjb + i * 8);
        float4 A1 = *(const float4*)(adjb + i * 8 + 4);
        float s = A0.x * u[0];
        s = fmaf(A0.y, u[1], s); s = fmaf(A0.z, u[2], s); s = fmaf(A0.w, u[3], s);
        s = fmaf(A1.x, u[4], s); s = fmaf(A1.y, u[5], s); s = fmaf(A1.z, u[6], s);
        s = fmaf(A1.w, u[7], s);
        float c[8], is;
        if (s != 0.f) {                       // warp-uniform branch
            is = __fdividef(1.f, s);
            c[0] = A0.x * w[0]; c[1] = A0.y * w[1]; c[2] = A0.z * w[2]; c[3] = A0.w * w[3];
            c[4] = A1.x * w[4]; c[5] = A1.y * w[5]; c[6] = A1.z * w[6]; c[7] = A1.w * w[7];
        } else {                              // fully-masked row: uniform 1/8
            is = 0.125f;
#pragma unroll
            for (int j = 0; j < 8; j++) c[j] = scale[j];
        }
        float4 g = make_float4(0.f, 0.f, 0.f, 0.f);
#pragma unroll
        for (int j = 0; j < 8; j++) {
            g.x = fmaf(c[j], hv[j].x, g.x);
            g.y = fmaf(c[j], hv[j].y, g.y);
            g.z = fmaf(c[j], hv[j].z, g.z);
            g.w = fmaf(c[j], hv[j].w, g.w);
        }
        g.x *= is; g.y *= is; g.z *= is; g.w *= is;

        __half2 h01 = __floats2half2_rn(g.x, g.y);
        __half2 h23 = __floats2half2_rn(g.z, g.w);
        uint2 uh = make_uint2(*(u32*)&h01, *(u32*)&h23);
        *(uint2*)(Ah + (row_base + i) * ROWB + lane * 8) = uh;
    }
}

__global__ __launch_bounds__(256, 3) void fused_gat_hmma(
    const float* __restrict__ h, const float* __restrict__ adj,
    const float* __restrict__ a_node, float* __restrict__ out)
{
    extern __shared__ char sm[];
    const u32 smb = smem_u32(sm);
    int tid = threadIdx.x, lane = tid & 31, warp = tid >> 5;
    int quad = warp >> 2, qw = warp & 3;     // 2 quads/CTA, 4 warps each

    // ---- stage W^T (fp16) into padded smem, once per CTA ----
    {
        const uint4* Wh = (const uint4*)d_Whi;   // 2048 16B chunks
#pragma unroll
        for (int t = 0; t < 8; t++) {
            int idx = tid + t * 256;
            int row = idx >> 4, c = idx & 15;
            *(uint4*)(sm + OFF_WH + row * ROWB + c * 16) = Wh[idx];
        }
    }
    __syncthreads();

    float4 an = *(const float4*)(a_node + lane * 4);
    float4 v1 = *(const float4*)(d_wa1 + lane * 4);

    char* Ah = sm + OFF_A + quad * PANELB;   // 32 rows = quad's 4 batches
    const int bq = blockIdx.x * 8 + quad * 4;   // quad's first batch
    const int b = bq + qw;                      // this warp's batch
    const int rb = qw * 8;

    // ---- this batch's h loads issued upfront ----
    float4 hv[8];
    {
        const float* hb = h + (size_t)b * 1024;
#pragma unroll
        for (int j = 0; j < 8; j++) hv[j] = *(const float4*)(hb + j * 128 + lane * 4);
    }

    attention_fold(hv, adj + (size_t)b * 64, an, v1, lane, Ah, rb);

    // quad barrier: all 4 warps' A rows visible before cross-read
    asm volatile("bar.sync %0, 128;" :: "r"(quad + 1) : "memory");

    // ====== HMMA GEMM: rows 0..31 (quad's 4 batches) x this warp's 32-col quarter ======
    float acc[8][4];   // [mt*4+nt][c]
#pragma unroll
    for (int t = 0; t < 8; t++) { acc[t][0] = acc[t][1] = acc[t][2] = acc[t][3] = 0.f; }

    const u32 ah_base = smb + (u32)(OFF_A + quad * PANELB);
    const u32 a_off = (u32)((lane & 15) * ROWB + (lane >> 4) * 16);
    // B row n = qw*32 + np*16 + (lane>>4)*8 + (lane&7); +16B if (lane>>3)&1
    const u32 b_off = (u32)((qw * 32 + ((lane >> 4) << 3) + (lane & 7)) * ROWB +
                            (((lane >> 3) & 1) << 4));

#pragma unroll
    for (int ks = 0; ks < 8; ks++) {
        u32 afh[2][4];
#pragma unroll
        for (int mt = 0; mt < 2; mt++)
            ldsm4(afh[mt], ah_base + a_off + mt * (16 * ROWB) + ks * 32);
#pragma unroll
        for (int np = 0; np < 2; np++) {
            u32 bh[4];
            ldsm4(bh, smb + (u32)OFF_WH + (u32)(np * 16 * ROWB) + b_off + ks * 32);
#pragma unroll
            for (int mt = 0; mt < 2; mt++) {
                mma16816(acc[mt * 4 + 2 * np],     afh[mt], bh[0], bh[1]);
                mma16816(acc[mt * 4 + 2 * np + 1], afh[mt], bh[2], bh[3]);
            }
        }
    }

    // ---- epilogue: relu + store ----
    // acc[mt*4+nt]: c0,c1 -> batch bq+mt*2,   m-row lane>>2
    //               c2,c3 -> batch bq+mt*2+1, m-row lane>>2
    // col = qw*32 + nt*8 + (lane&3)*2
#pragma unroll
    for (int mt = 0; mt < 2; mt++) {
        float* o0 = out + ((size_t)(bq + mt * 2) * 8 + (lane >> 2)) * 128 +
                    qw * 32 + (lane & 3) * 2;
        float* o1 = o0 + 1024;
#pragma unroll
        for (int nt = 0; nt < 4; nt++) {
            float* ac = acc[mt * 4 + nt];
            float2 r0 = make_float2(fmaxf(ac[0], 0.f), fmaxf(ac[1], 0.f));
            float2 r1 = make_float2(fmaxf(ac[2], 0.f), fmaxf(ac[3], 0.f));
            *(float2*)(o0 + nt * 8) = r0;
            *(float2*)(o1 + nt * 8) = r1;
        }
    }
}

extern "C" void kernel_launch(void* const* d_in, const int* in_sizes, int n_in,
                              void* d_out, int out_size) {
    const float* h      = (const float*)d_in[0];
    const float* adj    = (const float*)d_in[1];
    const float* W      = (const float*)d_in[2];
    const float* a      = (const float*)d_in[3];
    const float* a_node = (const float*)d_in[4];
    float* out = (float*)d_out;

    prep_kernel<<<192, 256>>>(W, a);

    cudaFuncSetAttribute(fused_gat_hmma, cudaFuncAttributeMaxDynamicSharedMemorySize, SMEM_BYTES);
    fused_gat_hmma<<<B_TOT / 8, 256, SMEM_BYTES>>>(h, adj, a_node, out);
}